// round 3
// baseline (speedup 1.0000x reference)
#include <cuda_runtime.h>
#include <cuda_bf16.h>
#include <math.h>

// Problem constants
#define Hdim 1024
#define Idim 4096
#define NE   8
#define NT   2048      // B*S tokens
#define TOPK 2
#define NSLOT 6144     // 2*NT expert slots + NT shared-expert slots
#define SHOFF 4096     // start of shared-expert slots

// ---------------- scratch (static __device__ globals; no allocation) ----------
__device__ float g_hact[(size_t)NSLOT * Idim];   // post-GELU activations, ~100 MB
__device__ float g_eo[(size_t)NSLOT * Hdim];     // pre-weighted down outputs, ~25 MB
__device__ int   g_slot_token[NSLOT];
__device__ float g_slot_weight[NSLOT];
__device__ int   g_expert_off[10];               // offsets for 9 virtual experts (+end)
__device__ int   g_tok_slot[NT * 2];
__device__ int   g_tok_eidx[NT * 2];
__device__ float g_tok_w[NT * 2];

// ---------------- gating: 1 warp per token ------------------------------------
__global__ __launch_bounds__(256) void gate_kernel(
    const float* __restrict__ x, const float* __restrict__ gate_w,
    const float* __restrict__ gbias) {
  int warp = threadIdx.x >> 5;
  int lane = threadIdx.x & 31;
  int t = blockIdx.x * 8 + warp;
  if (t >= NT) return;
  const float* xr = x + (size_t)t * Hdim;
  float s[NE] = {0.f,0.f,0.f,0.f,0.f,0.f,0.f,0.f};
  for (int k = lane; k < Hdim; k += 32) {
    float xv = xr[k];
    const float* gw = gate_w + k * NE;
#pragma unroll
    for (int e = 0; e < NE; e++) s[e] += xv * gw[e];
  }
#pragma unroll
  for (int e = 0; e < NE; e++) {
#pragma unroll
    for (int o = 16; o > 0; o >>= 1) s[e] += __shfl_xor_sync(0xffffffffu, s[e], o);
  }
  if (lane == 0) {
    float sc[NE];
#pragma unroll
    for (int e = 0; e < NE; e++) sc[e] = 1.0f / (1.0f + expf(-(s[e] + gbias[e])));
    // top-2 (strict > keeps lowest index on ties, matching jax top_k)
    int i0 = 0;
#pragma unroll
    for (int e = 1; e < NE; e++) if (sc[e] > sc[i0]) i0 = e;
    int i1 = (i0 == 0) ? 1 : 0;
#pragma unroll
    for (int e = 0; e < NE; e++) if (e != i0 && sc[e] > sc[i1]) i1 = e;
    float denom = sc[i0] + sc[i1] + 1e-6f;
    g_tok_eidx[t * 2 + 0] = i0;
    g_tok_eidx[t * 2 + 1] = i1;
    g_tok_w[t * 2 + 0] = sc[i0] / denom;
    g_tok_w[t * 2 + 1] = sc[i1] / denom;
  }
}

// ---------------- routing: deterministic, atomic-free compaction --------------
__global__ __launch_bounds__(256) void route_kernel() {
  __shared__ int counts[NE];
  __shared__ int offs[NE + 1];
  int wid = threadIdx.x >> 5;
  int lane = threadIdx.x & 31;
  if (wid < NE) {
    int cnt = 0;
    for (int t0 = 0; t0 < NT; t0 += 32) {
      int t = t0 + lane;
      bool m = (g_tok_eidx[t * 2] == wid) || (g_tok_eidx[t * 2 + 1] == wid);
      cnt += __popc(__ballot_sync(0xffffffffu, m));
    }
    if (lane == 0) counts[wid] = cnt;
  }
  __syncthreads();
  if (threadIdx.x == 0) {
    int o = 0;
    for (int e = 0; e < NE; e++) { offs[e] = o; g_expert_off[e] = o; o += counts[e]; }
    offs[NE] = o;                    // always 4096 (each token -> exactly 2 slots)
    g_expert_off[NE] = SHOFF;        // shared expert start
    g_expert_off[NE + 1] = SHOFF + NT;
  }
  __syncthreads();
  if (wid < NE) {
    int pos = offs[wid];
    for (int t0 = 0; t0 < NT; t0 += 32) {
      int t = t0 + lane;
      int e0 = g_tok_eidx[t * 2], e1 = g_tok_eidx[t * 2 + 1];
      int k = (e0 == wid) ? 0 : ((e1 == wid) ? 1 : -1);
      unsigned mask = __ballot_sync(0xffffffffu, k >= 0);
      if (k >= 0) {
        int slot = pos + __popc(mask & ((1u << lane) - 1u));
        g_slot_token[slot] = t;
        g_slot_weight[slot] = g_tok_w[t * 2 + k];
        g_tok_slot[t * 2 + k] = slot;
      }
      pos += __popc(mask);
    }
  }
  for (int t = threadIdx.x; t < NT; t += blockDim.x) {
    g_slot_token[SHOFF + t] = t;
    g_slot_weight[SHOFF + t] = 1.0f;
  }
}

// ---------------- fused grouped GEMM core --------------------------------------
// C[m][n] = sum_k A[m][k] * B[k][n]  with per-virtual-expert A rows and B matrix.
// 128x128 tile, BK=8, 256 threads, 8x8 microtile, smem double buffered.
// GATHER: A rows are x[token] gathered via slot list (up pass).
//         otherwise A rows are contiguous g_hact slots (down pass).
// IS_UP:  epilogue = GELU(acc + bias) -> g_hact
//         else      epilogue = (acc + bias) * 0.1 * slot_weight -> g_eo
template <int KDIM, int NDIM, bool GATHER, bool IS_UP>
__global__ __launch_bounds__(256, 2) void ffn_gemm(
    const float* __restrict__ Abase,   // x when GATHER, unused otherwise
    const float* __restrict__ Wexp,    // [NE, KDIM, NDIM]
    const float* __restrict__ Bexp,    // [NE, NDIM]
    const float* __restrict__ Wsh,     // [KDIM, NDIM]
    const float* __restrict__ Bsh) {   // [NDIM]
  int e = blockIdx.z;
  int start = g_expert_off[e];
  int count = g_expert_off[e + 1] - start;
  int m0 = blockIdx.y * 128;
  if (m0 >= count) return;
  int n0 = blockIdx.x * 128;

  const float* Bmat = (e < NE) ? (Wexp + (size_t)e * KDIM * NDIM) : Wsh;
  const float* bias = (e < NE) ? (Bexp + (size_t)e * NDIM) : Bsh;

  __shared__ float As[2][8][128];
  __shared__ float Bs[2][8][128];

  const int tid = threadIdx.x;
  const int arow = tid >> 1;          // 0..127
  const int akc  = (tid & 1) << 2;    // 0 or 4
  const int brow = tid >> 5;          // 0..7
  const int bcol = (tid & 31) << 2;   // 0..124
  const int ty = tid >> 4;            // 0..15
  const int tx = tid & 15;            // 0..15

  const float* aptr = nullptr;
  int gm = m0 + arow;
  if (gm < count) {
    if (GATHER) {
      int tok = g_slot_token[start + gm];
      aptr = Abase + (size_t)tok * KDIM;
    } else {
      aptr = g_hact + (size_t)(start + gm) * KDIM;
    }
  }

  float acc[8][8];
#pragma unroll
  for (int i = 0; i < 8; i++)
#pragma unroll
    for (int j = 0; j < 8; j++) acc[i][j] = 0.0f;

  // prologue: tile 0
  float4 aR = aptr ? *(const float4*)(aptr + akc) : make_float4(0.f, 0.f, 0.f, 0.f);
  float4 bR = *(const float4*)(Bmat + (size_t)brow * NDIM + n0 + bcol);
  As[0][akc + 0][arow] = aR.x;
  As[0][akc + 1][arow] = aR.y;
  As[0][akc + 2][arow] = aR.z;
  As[0][akc + 3][arow] = aR.w;
  *(float4*)&Bs[0][brow][bcol] = bR;
  __syncthreads();

  int buf = 0;
  const int KT = KDIM / 8;
  for (int kt = 0; kt < KT; kt++) {
    const bool more = (kt + 1 < KT);
    if (more) {
      int k0 = (kt + 1) * 8;
      aR = aptr ? *(const float4*)(aptr + k0 + akc) : make_float4(0.f, 0.f, 0.f, 0.f);
      bR = *(const float4*)(Bmat + (size_t)(k0 + brow) * NDIM + n0 + bcol);
    }
#pragma unroll
    for (int k = 0; k < 8; k++) {
      float4 a0 = *(const float4*)&As[buf][k][ty * 8];
      float4 a1 = *(const float4*)&As[buf][k][ty * 8 + 4];
      float4 b0 = *(const float4*)&Bs[buf][k][tx * 8];
      float4 b1 = *(const float4*)&Bs[buf][k][tx * 8 + 4];
      float av[8] = {a0.x, a0.y, a0.z, a0.w, a1.x, a1.y, a1.z, a1.w};
      float bv[8] = {b0.x, b0.y, b0.z, b0.w, b1.x, b1.y, b1.z, b1.w};
#pragma unroll
      for (int i = 0; i < 8; i++)
#pragma unroll
        for (int j = 0; j < 8; j++) acc[i][j] = fmaf(av[i], bv[j], acc[i][j]);
    }
    if (more) {
      buf ^= 1;
      As[buf][akc + 0][arow] = aR.x;
      As[buf][akc + 1][arow] = aR.y;
      As[buf][akc + 2][arow] = aR.z;
      As[buf][akc + 3][arow] = aR.w;
      *(float4*)&Bs[buf][brow][bcol] = bR;
      __syncthreads();
    }
  }

  // epilogue: bias cached once, results packed to float4 stores
  float bv[8];
#pragma unroll
  for (int j = 0; j < 8; j++) bv[j] = bias[n0 + tx * 8 + j];
#pragma unroll
  for (int i = 0; i < 8; i++) {
    int rm = m0 + ty * 8 + i;
    if (rm >= count) continue;
    int slot = start + rm;
    float r[8];
    if (IS_UP) {
#pragma unroll
      for (int j = 0; j < 8; j++) {
        float v = acc[i][j] + bv[j];
        r[j] = 0.5f * v * (1.0f + erff(v * 0.70710678118654752440f));
      }
      float* op = g_hact + (size_t)slot * Idim + n0 + tx * 8;
      *(float4*)(op)     = make_float4(r[0], r[1], r[2], r[3]);
      *(float4*)(op + 4) = make_float4(r[4], r[5], r[6], r[7]);
    } else {
      float wscale = 0.1f * g_slot_weight[slot];
#pragma unroll
      for (int j = 0; j < 8; j++) r[j] = (acc[i][j] + bv[j]) * wscale;
      float* op = g_eo + (size_t)slot * Hdim + n0 + tx * 8;
      *(float4*)(op)     = make_float4(r[0], r[1], r[2], r[3]);
      *(float4*)(op + 4) = make_float4(r[4], r[5], r[6], r[7]);
    }
  }
}

// ---------------- combine + per-token max-abs normalization --------------------
__global__ __launch_bounds__(256) void combine_kernel(float* __restrict__ out) {
  int t = blockIdx.x;
  int s0 = g_tok_slot[t * 2 + 0];
  int s1 = g_tok_slot[t * 2 + 1];
  const float* r0 = g_eo + (size_t)(SHOFF + t) * Hdim;  // shared expert (weight 1)
  const float* ra = g_eo + (size_t)s0 * Hdim;
  const float* rb = g_eo + (size_t)s1 * Hdim;
  float v[4];
  float mx = 0.0f;
#pragma unroll
  for (int i = 0; i < 4; i++) {
    int h = threadIdx.x + i * 256;
    float val = r0[h] + ra[h] + rb[h];
    v[i] = val;
    mx = fmaxf(mx, fabsf(val));
  }
#pragma unroll
  for (int o = 16; o > 0; o >>= 1) mx = fmaxf(mx, __shfl_xor_sync(0xffffffffu, mx, o));
  __shared__ float smax[8];
  __shared__ float bmax;
  if ((threadIdx.x & 31) == 0) smax[threadIdx.x >> 5] = mx;
  __syncthreads();
  if (threadIdx.x == 0) {
    float m = smax[0];
#pragma unroll
    for (int w = 1; w < 8; w++) m = fmaxf(m, smax[w]);
    bmax = m;
  }
  __syncthreads();
  float inv = 1.0f / (bmax + 1e-6f);
  float* op = out + (size_t)t * Hdim;
#pragma unroll
  for (int i = 0; i < 4; i++) op[threadIdx.x + i * 256] = v[i] * inv;
}

// ---------------- launch --------------------------------------------------------
extern "C" void kernel_launch(void* const* d_in, const int* in_sizes, int n_in,
                              void* d_out, int out_size) {
  const float* x       = (const float*)d_in[0];   // [2,1024,1024]
  const float* gate_w  = (const float*)d_in[1];   // [1024,8]
  const float* bias    = (const float*)d_in[2];   // [8]
  const float* up_w    = (const float*)d_in[3];   // [8,1024,4096]
  const float* up_b    = (const float*)d_in[4];   // [8,4096]
  const float* down_w  = (const float*)d_in[5];   // [8,4096,1024]
  const float* down_b  = (const float*)d_in[6];   // [8,1024]
  const float* sw_up   = (const float*)d_in[7];   // [1024,4096]
  const float* sb_up   = (const float*)d_in[8];   // [4096]
  const float* sw_down = (const float*)d_in[9];   // [4096,1024]
  const float* sb_down = (const float*)d_in[10];  // [1024]
  float* out = (float*)d_out;

  gate_kernel<<<NT / 8, 256>>>(x, gate_w, bias);
  route_kernel<<<1, 256>>>();

  // up: [rows up to 2048 per virtual expert] x [I=4096], K=1024
  dim3 gUp(Idim / 128, NT / 128, 9);
  ffn_gemm<Hdim, Idim, true, true><<<gUp, 256>>>(x, up_w, up_b, sw_up, sb_up);

  // down: rows x [H=1024], K=4096
  dim3 gDn(Hdim / 128, NT / 128, 9);
  ffn_gemm<Idim, Hdim, false, false><<<gDn, 256>>>(nullptr, down_w, down_b, sw_down, sb_down);

  combine_kernel<<<NT, 256>>>(out);
}

// round 7
// speedup vs baseline: 3.2996x; 3.2996x over previous
#include <cuda_runtime.h>
#include <cuda_bf16.h>
#include <math.h>
#include <stdint.h>

// Problem constants
#define Hdim 1024
#define Idim 4096
#define NE   8
#define NT   2048
#define NSLOT 6144
#define SHOFF 4096

// ---------------- scratch ------------------------------------------------------
__device__ float g_hact[(size_t)NSLOT * Idim];
__device__ float g_eo[(size_t)NSLOT * Hdim];
__device__ int   g_slot_token[NSLOT];
__device__ float g_slot_weight[NSLOT];
__device__ int   g_expert_off[10];
__device__ int   g_tok_slot[NT * 2];
__device__ int   g_tok_eidx[NT * 2];
__device__ float g_tok_w[NT * 2];

// ---------------- helpers ------------------------------------------------------
__device__ __forceinline__ uint32_t smem_u32(const void* p) {
  uint32_t r;
  asm("{ .reg .u64 t; cvta.to.shared.u64 t, %1; cvt.u32.u64 %0, t; }" : "=r"(r) : "l"(p));
  return r;
}
__device__ __forceinline__ void cp16(uint32_t s, const void* g) {
  asm volatile("cp.async.cg.shared.global [%0], [%1], 16;" :: "r"(s), "l"(g));
}
#define CP_COMMIT() asm volatile("cp.async.commit_group;" ::: "memory")
#define CP_WAIT(n)  asm volatile("cp.async.wait_group %0;" :: "n"(n) : "memory")

__device__ __forceinline__ uint32_t tf32cvt(float f) {
  uint32_t u;
  asm("cvt.rna.tf32.f32 %0, %1;" : "=r"(u) : "f"(f));
  return u;
}
__device__ __forceinline__ void mma8(float* c, const uint32_t* a, uint32_t b0, uint32_t b1) {
  asm volatile(
      "mma.sync.aligned.m16n8k8.row.col.f32.tf32.tf32.f32 "
      "{%0,%1,%2,%3},{%4,%5,%6,%7},{%8,%9},{%0,%1,%2,%3};"
      : "+f"(c[0]), "+f"(c[1]), "+f"(c[2]), "+f"(c[3])
      : "r"(a[0]), "r"(a[1]), "r"(a[2]), "r"(a[3]), "r"(b0), "r"(b1));
}

// ---------------- gating -------------------------------------------------------
__global__ __launch_bounds__(256) void gate_kernel(
    const float* __restrict__ x, const float* __restrict__ gate_w,
    const float* __restrict__ gbias) {
  int warp = threadIdx.x >> 5, lane = threadIdx.x & 31;
  int t = blockIdx.x * 8 + warp;
  if (t >= NT) return;
  const float* xr = x + (size_t)t * Hdim;
  float s[NE] = {0.f,0.f,0.f,0.f,0.f,0.f,0.f,0.f};
  for (int k = lane; k < Hdim; k += 32) {
    float xv = xr[k];
    const float* gw = gate_w + k * NE;
#pragma unroll
    for (int e = 0; e < NE; e++) s[e] += xv * gw[e];
  }
#pragma unroll
  for (int e = 0; e < NE; e++)
#pragma unroll
    for (int o = 16; o > 0; o >>= 1) s[e] += __shfl_xor_sync(0xffffffffu, s[e], o);
  if (lane == 0) {
    float sc[NE];
#pragma unroll
    for (int e = 0; e < NE; e++) sc[e] = 1.0f / (1.0f + expf(-(s[e] + gbias[e])));
    int i0 = 0;
#pragma unroll
    for (int e = 1; e < NE; e++) if (sc[e] > sc[i0]) i0 = e;
    int i1 = (i0 == 0) ? 1 : 0;
#pragma unroll
    for (int e = 0; e < NE; e++) if (e != i0 && sc[e] > sc[i1]) i1 = e;
    float denom = sc[i0] + sc[i1] + 1e-6f;
    g_tok_eidx[t*2+0] = i0;  g_tok_eidx[t*2+1] = i1;
    g_tok_w[t*2+0] = sc[i0] / denom;  g_tok_w[t*2+1] = sc[i1] / denom;
  }
}

// ---------------- routing ------------------------------------------------------
__global__ __launch_bounds__(256) void route_kernel() {
  __shared__ int counts[NE];
  __shared__ int offs[NE + 1];
  int wid = threadIdx.x >> 5, lane = threadIdx.x & 31;
  if (wid < NE) {
    int cnt = 0;
    for (int t0 = 0; t0 < NT; t0 += 32) {
      int t = t0 + lane;
      bool m = (g_tok_eidx[t*2] == wid) || (g_tok_eidx[t*2+1] == wid);
      cnt += __popc(__ballot_sync(0xffffffffu, m));
    }
    if (lane == 0) counts[wid] = cnt;
  }
  __syncthreads();
  if (threadIdx.x == 0) {
    int o = 0;
    for (int e = 0; e < NE; e++) { offs[e] = o; g_expert_off[e] = o; o += counts[e]; }
    offs[NE] = o;
    g_expert_off[NE] = SHOFF;
    g_expert_off[NE + 1] = SHOFF + NT;
  }
  __syncthreads();
  if (wid < NE) {
    int pos = offs[wid];
    for (int t0 = 0; t0 < NT; t0 += 32) {
      int t = t0 + lane;
      int e0 = g_tok_eidx[t*2], e1 = g_tok_eidx[t*2+1];
      int k = (e0 == wid) ? 0 : ((e1 == wid) ? 1 : -1);
      unsigned mask = __ballot_sync(0xffffffffu, k >= 0);
      if (k >= 0) {
        int slot = pos + __popc(mask & ((1u << lane) - 1u));
        g_slot_token[slot] = t;
        g_slot_weight[slot] = g_tok_w[t*2+k];
        g_tok_slot[t*2+k] = slot;
      }
      pos += __popc(mask);
    }
  }
  for (int t = threadIdx.x; t < NT; t += blockDim.x) {
    g_slot_token[SHOFF + t] = t;
    g_slot_weight[SHOFF + t] = 1.0f;
  }
}

// ---------------- tf32 mma.sync grouped GEMM -----------------------------------
// 128x128 CTA tile, BK=32, 256 threads, 8 warps (4 M x 2 N), warp tile 32x64.
// smem (dynamic floats): A[2][128][36] @0 (stage stride 4608),
//                        B[2][32][136] @9216 (stage stride 4352). Total 71680 B.
#define SMEM_DYN 71680

template <int KDIM, int NDIM, bool GATHER, bool IS_UP>
__global__ __launch_bounds__(256, 1)
void moe_gemm(const float* __restrict__ Abase,
              const float* __restrict__ Wexp, const float* __restrict__ Bexp,
              const float* __restrict__ Wsh,  const float* __restrict__ Bsh) {
  extern __shared__ float sm[];
  int e = blockIdx.z;
  int start = g_expert_off[e];
  int count = g_expert_off[e + 1] - start;
  int m0 = blockIdx.y * 128;
  if (m0 >= count) return;
  int n0 = blockIdx.x * 128;

  const float* Bmat = (e < NE) ? (Wexp + (size_t)e * KDIM * NDIM) : Wsh;
  const float* bias = (e < NE) ? (Bexp + (size_t)e * NDIM) : Bsh;

  const int tid  = threadIdx.x;
  const int lane = tid & 31;
  const int wid  = tid >> 5;
  const int warpM = wid & 3;        // 0..3 -> M strips of 32
  const int warpN = wid >> 2;       // 0..1 -> N strips of 64
  const int g  = lane >> 2;         // 0..7
  const int cq = lane & 3;          // 0..3

  // A loader: 2 threads per row, each 4 float4 (16 floats)
  const int arow = tid >> 1;
  const int ahalf = tid & 1;
  int gmr = m0 + arow;
  int aidx = start + ((gmr < count) ? gmr : 0);
  const float* aptr;
  if (GATHER) aptr = Abase + (size_t)g_slot_token[aidx] * KDIM;
  else        aptr = g_hact + (size_t)aidx * KDIM;
  aptr += ahalf * 16;

  const uint32_t smb = smem_u32(sm);
  const uint32_t aDst = smb + arow * 144u + ahalf * 64u;   // byte addr within stage

  float acc[2][8][4];
#pragma unroll
  for (int mt = 0; mt < 2; mt++)
#pragma unroll
    for (int nt = 0; nt < 8; nt++)
#pragma unroll
      for (int q = 0; q < 4; q++) acc[mt][nt][q] = 0.0f;

  const int KT = KDIM / 32;

  // stage loader
  auto load_stage = [&](int s, int kb) {
    uint32_t ab = aDst + (uint32_t)s * 18432u;
    const float* ap = aptr + kb;
#pragma unroll
    for (int i = 0; i < 4; i++) cp16(ab + i * 16u, ap + i * 4);
    uint32_t bb = smb + 36864u + (uint32_t)s * 17408u;
#pragma unroll
    for (int i = 0; i < 4; i++) {
      int idx = tid + 256 * i;
      int kr = idx >> 5, c4 = idx & 31;
      cp16(bb + kr * 544u + c4 * 16u,
           Bmat + (size_t)(kb + kr) * NDIM + n0 + c4 * 4);
    }
    CP_COMMIT();
  };

  load_stage(0, 0);

  for (int kt = 0; kt < KT; kt++) {
    if (kt + 1 < KT) { load_stage((kt + 1) & 1, (kt + 1) * 32); CP_WAIT(1); }
    else             { CP_WAIT(0); }
    __syncthreads();

    const float* As = sm + (kt & 1) * 4608;
    const float* Bs = sm + 9216 + (kt & 1) * 4352;
#pragma unroll
    for (int ks = 0; ks < 4; ks++) {
      int kb = ks * 8;
      uint32_t a[2][4];
#pragma unroll
      for (int mt = 0; mt < 2; mt++) {
        int r = warpM * 32 + mt * 16;
        a[mt][0] = tf32cvt(As[(r + g)     * 36 + kb + cq]);
        a[mt][1] = tf32cvt(As[(r + 8 + g) * 36 + kb + cq]);
        a[mt][2] = tf32cvt(As[(r + g)     * 36 + kb + cq + 4]);
        a[mt][3] = tf32cvt(As[(r + 8 + g) * 36 + kb + cq + 4]);
      }
#pragma unroll
      for (int nt = 0; nt < 8; nt++) {
        int nc = warpN * 64 + nt * 8;
        uint32_t b0 = tf32cvt(Bs[(kb + cq)     * 136 + nc + g]);
        uint32_t b1 = tf32cvt(Bs[(kb + cq + 4) * 136 + nc + g]);
        mma8(acc[0][nt], a[0], b0, b1);
        mma8(acc[1][nt], a[1], b0, b1);
      }
    }
    __syncthreads();   // all warps done with this buffer before it is reloaded
  }

  // ---- epilogue: c0/c1 at row g, c2/c3 at row g+8; cols cq*2, cq*2+1 ----
#pragma unroll
  for (int mt = 0; mt < 2; mt++) {
#pragma unroll
    for (int half = 0; half < 2; half++) {
      int r = m0 + warpM * 32 + mt * 16 + g + half * 8;
      if (r >= count) continue;
      int slot = start + r;
      float wscale = IS_UP ? 0.0f : (0.1f * g_slot_weight[slot]);
      float* dstRow = IS_UP ? (g_hact + (size_t)slot * Idim)
                            : (g_eo   + (size_t)slot * Hdim);
#pragma unroll
      for (int nt = 0; nt < 8; nt++) {
        int col = n0 + warpN * 64 + nt * 8 + cq * 2;
        float v0 = acc[mt][nt][half * 2 + 0] + __ldg(bias + col);
        float v1 = acc[mt][nt][half * 2 + 1] + __ldg(bias + col + 1);
        if (IS_UP) {
          v0 = 0.5f * v0 * (1.0f + erff(v0 * 0.70710678118654752440f));
          v1 = 0.5f * v1 * (1.0f + erff(v1 * 0.70710678118654752440f));
        } else {
          v0 *= wscale;
          v1 *= wscale;
        }
        *(float2*)(dstRow + col) = make_float2(v0, v1);
      }
    }
  }
}

// ---------------- combine ------------------------------------------------------
__global__ __launch_bounds__(256) void combine_kernel(float* __restrict__ out) {
  int t = blockIdx.x;
  int s0 = g_tok_slot[t*2+0], s1 = g_tok_slot[t*2+1];
  const float* r0 = g_eo + (size_t)(SHOFF + t) * Hdim;
  const float* ra = g_eo + (size_t)s0 * Hdim;
  const float* rb = g_eo + (size_t)s1 * Hdim;
  float v[4], mx = 0.0f;
#pragma unroll
  for (int i = 0; i < 4; i++) {
    int h = threadIdx.x + i * 256;
    float val = r0[h] + ra[h] + rb[h];
    v[i] = val;
    mx = fmaxf(mx, fabsf(val));
  }
#pragma unroll
  for (int o = 16; o > 0; o >>= 1) mx = fmaxf(mx, __shfl_xor_sync(0xffffffffu, mx, o));
  __shared__ float smax[8];
  __shared__ float bmax;
  if ((threadIdx.x & 31) == 0) smax[threadIdx.x >> 5] = mx;
  __syncthreads();
  if (threadIdx.x == 0) {
    float m = smax[0];
#pragma unroll
    for (int w = 1; w < 8; w++) m = fmaxf(m, smax[w]);
    bmax = m;
  }
  __syncthreads();
  float inv = 1.0f / (bmax + 1e-6f);
  float* op = out + (size_t)t * Hdim;
#pragma unroll
  for (int i = 0; i < 4; i++) op[threadIdx.x + i * 256] = v[i] * inv;
}

// ---------------- launch -------------------------------------------------------
extern "C" void kernel_launch(void* const* d_in, const int* in_sizes, int n_in,
                              void* d_out, int out_size) {
  const float* x       = (const float*)d_in[0];
  const float* gate_w  = (const float*)d_in[1];
  const float* bias    = (const float*)d_in[2];
  const float* up_w    = (const float*)d_in[3];
  const float* up_b    = (const float*)d_in[4];
  const float* down_w  = (const float*)d_in[5];
  const float* down_b  = (const float*)d_in[6];
  const float* sw_up   = (const float*)d_in[7];
  const float* sb_up   = (const float*)d_in[8];
  const float* sw_down = (const float*)d_in[9];
  const float* sb_down = (const float*)d_in[10];
  float* out = (float*)d_out;

  cudaFuncSetAttribute(moe_gemm<Hdim, Idim, true, true>,
                       cudaFuncAttributeMaxDynamicSharedMemorySize, SMEM_DYN);
  cudaFuncSetAttribute(moe_gemm<Idim, Hdim, false, false>,
                       cudaFuncAttributeMaxDynamicSharedMemorySize, SMEM_DYN);

  gate_kernel<<<NT / 8, 256>>>(x, gate_w, bias);
  route_kernel<<<1, 256>>>();

  dim3 gUp(Idim / 128, NT / 128, 9);
  moe_gemm<Hdim, Idim, true, true><<<gUp, 256, SMEM_DYN>>>(x, up_w, up_b, sw_up, sb_up);

  dim3 gDn(Hdim / 128, NT / 128, 9);
  moe_gemm<Idim, Hdim, false, false><<<gDn, 256, SMEM_DYN>>>(nullptr, down_w, down_b, sw_down, sb_down);

  combine_kernel<<<NT, 256>>>(out);
}